// round 5
// baseline (speedup 1.0000x reference)
#include <cuda_runtime.h>
#include <math.h>

#define NN 200000
#define NE 5000000

// ---- scratch: plain __device__ globals (~40 MB) ----------------------------
__device__ int   g_cnt[NN];
__device__ float g_dis[NN];
__device__ float g_X[NN * 16];   // xl (linear output) for current layer
__device__ float g_A[NN * 16];   // aggregate ping
__device__ float g_B[NN * 16];   // aggregate pong

// ---- degree / normalization ------------------------------------------------
__global__ void zero_cnt_kernel() {
    int i = blockIdx.x * blockDim.x + threadIdx.x;
    if (i < NN) g_cnt[i] = 0;
}

// edge_index is INT32 (JAX default config demotes int64; harness dtypes are
// float32/int32/bf16 only). Guard indices: wrong values must yield wrong
// numbers (finite rel_err), never a wild-address trap.
__global__ void count_deg_kernel(const int* ei) {
    int e = blockIdx.x * blockDim.x + threadIdx.x;
    if (e < NE) {
        int d = ei[NE + e];
        if ((unsigned)d < NN) atomicAdd(&g_cnt[d], 1);
    }
}

__global__ void dis_kernel() {
    int i = blockIdx.x * blockDim.x + threadIdx.x;
    if (i < NN) {
        // degree includes self-loop: cnt+1 >= 1, so no zero guard needed
        g_dis[i] = rsqrtf((float)(g_cnt[i] + 1));
    }
}

// ---- fused (prev bias + act) -> linear -> self-loop init --------------------
// INSEL: 0 = external x, 1 = g_A, 2 = g_B ; OUTSEL: 1 = g_A, 2 = g_B
template <int FIN, int FOUT, int ACT, int HASB, int INSEL, int OUTSEL>
__global__ void lin_kernel(const float* xarg, const float* W, const float* bprev) {
    const float* in = (INSEL == 0) ? xarg : (INSEL == 1 ? g_A : g_B);
    float* agg = (OUTSEL == 1) ? g_A : g_B;

    __shared__ float sW[FIN * FOUT];
    __shared__ float sb[16];
    int t = threadIdx.x;
    if (t < FIN * FOUT) sW[t] = W[t];
    if (HASB && t < FIN) sb[t] = bprev[t];
    __syncthreads();

    int i = blockIdx.x * blockDim.x + t;
    if (i >= NN) return;

    float xin[FIN];
#pragma unroll
    for (int k = 0; k < FIN; k++) {
        float v = in[i * FIN + k];
        if (HASB) v += sb[k];
        if (ACT) v = fmaxf(v, 0.0f);
        xin[k] = v;
    }

    float o[FOUT];
#pragma unroll
    for (int f = 0; f < FOUT; f++) o[f] = 0.0f;
#pragma unroll
    for (int k = 0; k < FIN; k++) {
#pragma unroll
        for (int f = 0; f < FOUT; f++) o[f] = fmaf(xin[k], sW[k * FOUT + f], o[f]);
    }

    float d = g_dis[i];
    float d2 = d * d;  // self-loop norm = dis[i]^2
#pragma unroll
    for (int f = 0; f < FOUT; f++) {
        g_X[i * FOUT + f] = o[f];
        agg[i * FOUT + f] = o[f] * d2;
    }
}

// ---- edge scatter: agg[dst,f] += X[src,f] * dis[src]*dis[dst] ---------------
// thread = (edge, feature); one scalar atomicAdd per thread. Threads of the
// same edge are adjacent -> ei/dis loads broadcast, X/agg accesses coalesced.
template <int FOUT, int OUTSEL>
__global__ void scatter_kernel(const int* ei) {
    float* agg = (OUTSEL == 1) ? g_A : g_B;
    long long idx = (long long)blockIdx.x * blockDim.x + threadIdx.x;
    if (idx >= (long long)NE * FOUT) return;
    int e = (int)(idx / FOUT);
    int f = (int)(idx - (long long)e * FOUT);
    int s = ei[e];
    int d = ei[NE + e];
    if ((unsigned)s >= NN || (unsigned)d >= NN) return;  // trap-proof guard
    float nm = g_dis[s] * g_dis[d];
    float v = g_X[s * FOUT + f] * nm;
    atomicAdd(&agg[d * FOUT + f], v);
}

// ---- epilogue: d_out = sigmoid(g_B + b4), plain stores only -----------------
__global__ void epilogue_kernel(float* out, const float* b4) {
    int idx = blockIdx.x * blockDim.x + threadIdx.x;
    if (idx >= NN * 12) return;
    int col = idx % 12;
    float v = g_B[idx] + b4[col];
    out[idx] = 1.0f / (1.0f + expf(-v));
}

// ---- launch -----------------------------------------------------------------
extern "C" void kernel_launch(void* const* d_in, const int* in_sizes, int n_in,
                              void* d_out, int out_size) {
    const float* x  = (const float*)d_in[0];
    const int*   ei = (const int*)d_in[1];   // int32 edge_index [2, E]
    const float* W1 = (const float*)d_in[2]; const float* b1 = (const float*)d_in[3];
    const float* W2 = (const float*)d_in[4]; const float* b2 = (const float*)d_in[5];
    const float* W3 = (const float*)d_in[6]; const float* b3 = (const float*)d_in[7];
    const float* W4 = (const float*)d_in[8]; const float* b4 = (const float*)d_in[9];
    float* out = (float*)d_out;

    const int BT = 256;
    const int gN = (NN + BT - 1) / BT;
    const int gE = (NE + BT - 1) / BT;

    zero_cnt_kernel<<<gN, BT>>>();
    count_deg_kernel<<<gE, BT>>>(ei);
    dis_kernel<<<gN, BT>>>();

    // Layer 1: x -> W1 -> agg A
    lin_kernel<12, 16, 0, 0, 0, 1><<<gN, BT>>>(x, W1, 0);
    {
        long long tot = (long long)NE * 16;
        scatter_kernel<16, 1><<<(int)((tot + BT - 1) / BT), BT>>>(ei);
    }
    // Layer 2: relu(A + b1) -> W2 -> agg B
    lin_kernel<16, 8, 1, 1, 1, 2><<<gN, BT>>>(0, W2, b1);
    {
        long long tot = (long long)NE * 8;
        scatter_kernel<8, 2><<<(int)((tot + BT - 1) / BT), BT>>>(ei);
    }
    // Layer 3: (B + b2) -> W3 -> agg A
    lin_kernel<8, 16, 0, 1, 2, 1><<<gN, BT>>>(0, W3, b2);
    {
        long long tot = (long long)NE * 16;
        scatter_kernel<16, 1><<<(int)((tot + BT - 1) / BT), BT>>>(ei);
    }
    // Layer 4: relu(A + b3) -> W4 -> agg B
    lin_kernel<16, 12, 1, 1, 1, 2><<<gN, BT>>>(0, W4, b3);
    {
        long long tot = (long long)NE * 12;
        scatter_kernel<12, 2><<<(int)((tot + BT - 1) / BT), BT>>>(ei);
    }
    // out = sigmoid(B + b4)
    epilogue_kernel<<<(NN * 12 + BT - 1) / BT, BT>>>(out, b4);
}

// round 6
// speedup vs baseline: 1.2483x; 1.2483x over previous
#include <cuda_runtime.h>
#include <math.h>

#define NN 200000
#define NE 5000000

// ---- scratch: plain __device__ globals (~40 MB) ----------------------------
__device__ int   g_cnt[NN];
__device__ float g_dis[NN];
__device__ float g_X[NN * 16];   // xl (linear output) for current layer
__device__ float g_A[NN * 16];   // aggregate ping
__device__ float g_B[NN * 16];   // aggregate pong

// ---- degree / normalization ------------------------------------------------
__global__ void zero_cnt_kernel() {
    int i = blockIdx.x * blockDim.x + threadIdx.x;
    if (i < NN) g_cnt[i] = 0;
}

__global__ void count_deg_kernel(const int* __restrict__ ei) {
    int e = blockIdx.x * blockDim.x + threadIdx.x;
    if (e < NE) {
        int d = ei[NE + e];
        if ((unsigned)d < NN) atomicAdd(&g_cnt[d], 1);
    }
}

__global__ void dis_kernel() {
    int i = blockIdx.x * blockDim.x + threadIdx.x;
    if (i < NN) {
        g_dis[i] = rsqrtf((float)(g_cnt[i] + 1));  // self-loop included
    }
}

// ---- fused (prev bias + act) -> linear -> self-loop init --------------------
// INSEL: 0 = external x, 1 = g_A, 2 = g_B ; OUTSEL: 1 = g_A, 2 = g_B
template <int FIN, int FOUT, int ACT, int HASB, int INSEL, int OUTSEL>
__global__ void lin_kernel(const float* __restrict__ xarg,
                           const float* __restrict__ W,
                           const float* __restrict__ bprev) {
    const float* in = (INSEL == 0) ? xarg : (INSEL == 1 ? g_A : g_B);
    float* agg = (OUTSEL == 1) ? g_A : g_B;

    __shared__ float sW[FIN * FOUT];
    __shared__ float sb[16];
    int t = threadIdx.x;
    if (t < FIN * FOUT) sW[t] = W[t];
    if (HASB && t < FIN) sb[t] = bprev[t];
    __syncthreads();

    int i = blockIdx.x * blockDim.x + t;
    if (i >= NN) return;

    // row base is 16B aligned for FIN in {8,12,16}
    float xin[FIN];
    const float4* ip = (const float4*)(in + (size_t)i * FIN);
#pragma unroll
    for (int c = 0; c < FIN / 4; c++) {
        float4 v = ip[c];
        xin[4 * c + 0] = v.x; xin[4 * c + 1] = v.y;
        xin[4 * c + 2] = v.z; xin[4 * c + 3] = v.w;
    }
#pragma unroll
    for (int k = 0; k < FIN; k++) {
        float v = xin[k];
        if (HASB) v += sb[k];
        if (ACT) v = fmaxf(v, 0.0f);
        xin[k] = v;
    }

    float o[FOUT];
#pragma unroll
    for (int f = 0; f < FOUT; f++) o[f] = 0.0f;
#pragma unroll
    for (int k = 0; k < FIN; k++) {
#pragma unroll
        for (int f = 0; f < FOUT; f++) o[f] = fmaf(xin[k], sW[k * FOUT + f], o[f]);
    }

    float d = g_dis[i];
    float d2 = d * d;  // self-loop norm = dis[i]^2

    float4* xp = (float4*)(g_X + (size_t)i * FOUT);
    float4* ap = (float4*)(agg + (size_t)i * FOUT);
#pragma unroll
    for (int c = 0; c < FOUT / 4; c++) {
        float4 v;
        v.x = o[4 * c + 0]; v.y = o[4 * c + 1];
        v.z = o[4 * c + 2]; v.w = o[4 * c + 3];
        xp[c] = v;
        float4 a;
        a.x = v.x * d2; a.y = v.y * d2; a.z = v.z * d2; a.w = v.w * d2;
        ap[c] = a;
    }
}

// ---- vector reduction: agg[dst, 4c..4c+3] += xl[src, ...] * norm ------------
__device__ __forceinline__ void red_add_v4(float* p, float a, float b, float c, float d) {
    asm volatile("red.global.add.v4.f32 [%0], {%1, %2, %3, %4};"
                 :: "l"(p), "f"(a), "f"(b), "f"(c), "f"(d)
                 : "memory");
}

// thread = edge; FOUT/4 vector gathers + FOUT/4 vector reductions per edge
template <int FOUT, int OUTSEL>
__global__ void scatter_kernel(const int* __restrict__ ei) {
    float* agg = (OUTSEL == 1) ? g_A : g_B;
    int e = blockIdx.x * blockDim.x + threadIdx.x;
    if (e >= NE) return;
    int s = ei[e];
    int d = ei[NE + e];
    if ((unsigned)s >= NN || (unsigned)d >= NN) return;  // trap-proof guard
    float nm = g_dis[s] * g_dis[d];
    const float4* xr = (const float4*)(g_X + (size_t)s * FOUT);
    float* ar = agg + (size_t)d * FOUT;
#pragma unroll
    for (int c = 0; c < FOUT / 4; c++) {
        float4 v = xr[c];
        red_add_v4(ar + 4 * c, v.x * nm, v.y * nm, v.z * nm, v.w * nm);
    }
}

// ---- epilogue: d_out = sigmoid(g_B + b4), plain stores only -----------------
__global__ void epilogue_kernel(float4* __restrict__ out, const float* __restrict__ b4) {
    int q = blockIdx.x * blockDim.x + threadIdx.x;   // float4 index
    if (q >= NN * 12 / 4) return;
    const float4* bp = (const float4*)g_B;
    float4 v = bp[q];
    int base = (4 * q) % 12;  // 12 % 4 == 0, so base in {0,4,8}
    float b0 = b4[base + 0], b1 = b4[base + 1], b2 = b4[base + 2], b3 = b4[base + 3];
    float4 r;
    r.x = 1.0f / (1.0f + expf(-(v.x + b0)));
    r.y = 1.0f / (1.0f + expf(-(v.y + b1)));
    r.z = 1.0f / (1.0f + expf(-(v.z + b2)));
    r.w = 1.0f / (1.0f + expf(-(v.w + b3)));
    out[q] = r;
}

// ---- launch -----------------------------------------------------------------
extern "C" void kernel_launch(void* const* d_in, const int* in_sizes, int n_in,
                              void* d_out, int out_size) {
    const float* x  = (const float*)d_in[0];
    const int*   ei = (const int*)d_in[1];   // int32 edge_index [2, E]
    const float* W1 = (const float*)d_in[2]; const float* b1 = (const float*)d_in[3];
    const float* W2 = (const float*)d_in[4]; const float* b2 = (const float*)d_in[5];
    const float* W3 = (const float*)d_in[6]; const float* b3 = (const float*)d_in[7];
    const float* W4 = (const float*)d_in[8]; const float* b4 = (const float*)d_in[9];
    float* out = (float*)d_out;

    const int BT = 256;
    const int gN = (NN + BT - 1) / BT;
    const int gE = (NE + BT - 1) / BT;

    zero_cnt_kernel<<<gN, BT>>>();
    count_deg_kernel<<<gE, BT>>>(ei);
    dis_kernel<<<gN, BT>>>();

    // Layer 1: x -> W1 -> agg A
    lin_kernel<12, 16, 0, 0, 0, 1><<<gN, BT>>>(x, W1, 0);
    scatter_kernel<16, 1><<<gE, BT>>>(ei);

    // Layer 2: relu(A + b1) -> W2 -> agg B
    lin_kernel<16, 8, 1, 1, 1, 2><<<gN, BT>>>(0, W2, b1);
    scatter_kernel<8, 2><<<gE, BT>>>(ei);

    // Layer 3: (B + b2) -> W3 -> agg A
    lin_kernel<8, 16, 0, 1, 2, 1><<<gN, BT>>>(0, W3, b2);
    scatter_kernel<16, 1><<<gE, BT>>>(ei);

    // Layer 4: relu(A + b3) -> W4 -> agg B
    lin_kernel<16, 12, 1, 1, 1, 2><<<gN, BT>>>(0, W4, b3);
    scatter_kernel<12, 2><<<gE, BT>>>(ei);

    // out = sigmoid(B + b4)
    epilogue_kernel<<<(NN * 12 / 4 + BT - 1) / BT, BT>>>((float4*)out, b4);
}

// round 7
// speedup vs baseline: 2.5638x; 2.0539x over previous
#include <cuda_runtime.h>
#include <math.h>

#define NN 200000
#define NE 5000000
#define NBLK ((NN + 1023) / 1024)   // scan blocks (196)

// ---- scratch: plain __device__ globals (~85 MB) ----------------------------
__device__ int   g_cnt[NN];      // in-degree (without self-loop)
__device__ int   g_rowptr[NN];   // CSR row start
__device__ int   g_woff[NN];     // fill cursor
__device__ int   g_bsum[NBLK + 8];
__device__ int   g_boff[NBLK + 8];
__device__ float g_dis[NN];
__device__ int2  g_epack[NE];    // {src, norm-bits} sorted by dst
__device__ float g_X[NN * 16];   // xl (linear output) for current layer
__device__ float g_A[NN * 16];   // aggregate ping
__device__ float g_B[NN * 16];   // aggregate pong

// ---- degree ----------------------------------------------------------------
__global__ void zero_cnt_kernel() {
    int i = blockIdx.x * blockDim.x + threadIdx.x;
    if (i < NN) g_cnt[i] = 0;
}

__global__ void count_deg_kernel(const int* __restrict__ ei) {
    int e = blockIdx.x * blockDim.x + threadIdx.x;
    if (e < NE) {
        int d = ei[NE + e];
        if ((unsigned)d < NN) atomicAdd(&g_cnt[d], 1);
    }
}

__global__ void dis_kernel() {
    int i = blockIdx.x * blockDim.x + threadIdx.x;
    if (i < NN) g_dis[i] = rsqrtf((float)(g_cnt[i] + 1));  // self-loop included
}

// ---- exclusive prefix sum of g_cnt -> g_rowptr (3 kernels) ------------------
__global__ void scan1_kernel() {           // 1024 threads/block
    __shared__ int s[1024];
    int gid = blockIdx.x * 1024 + threadIdx.x;
    int v = (gid < NN) ? g_cnt[gid] : 0;
    s[threadIdx.x] = v;
    __syncthreads();
    for (int off = 1; off < 1024; off <<= 1) {
        int t = (threadIdx.x >= off) ? s[threadIdx.x - off] : 0;
        __syncthreads();
        s[threadIdx.x] += t;
        __syncthreads();
    }
    if (gid < NN) g_rowptr[gid] = s[threadIdx.x] - v;  // exclusive within block
    if (threadIdx.x == 1023) g_bsum[blockIdx.x] = s[1023];
}

__global__ void scan2_kernel() {           // 1 thread scans 196 block sums
    int acc = 0;
    for (int b = 0; b < NBLK; b++) { g_boff[b] = acc; acc += g_bsum[b]; }
}

__global__ void scan3_kernel() {           // add block offsets, init cursors
    int gid = blockIdx.x * blockDim.x + threadIdx.x;
    if (gid < NN) {
        int r = g_rowptr[gid] + g_boff[gid >> 10];
        g_rowptr[gid] = r;
        g_woff[gid] = r;
    }
}

// ---- CSR fill: bucket edges by dst, precompute norm -------------------------
__global__ void fill_csr_kernel(const int* __restrict__ ei) {
    int e = blockIdx.x * blockDim.x + threadIdx.x;
    if (e >= NE) return;
    int s = ei[e];
    int d = ei[NE + e];
    if ((unsigned)s >= NN || (unsigned)d >= NN) return;  // trap-proof guard
    float nm = g_dis[s] * g_dis[d];
    int pos = atomicAdd(&g_woff[d], 1);
    g_epack[pos] = make_int2(s, __float_as_int(nm));
}

// ---- (prev bias + act) -> linear -> X only ---------------------------------
// INSEL: 0 = external x, 1 = g_A, 2 = g_B
template <int FIN, int FOUT, int ACT, int HASB, int INSEL>
__global__ void lin_kernel(const float* __restrict__ xarg,
                           const float* __restrict__ W,
                           const float* __restrict__ bprev) {
    const float* in = (INSEL == 0) ? xarg : (INSEL == 1 ? g_A : g_B);

    __shared__ float sW[FIN * FOUT];
    __shared__ float sb[16];
    int t = threadIdx.x;
    if (t < FIN * FOUT) sW[t] = W[t];
    if (HASB && t < FIN) sb[t] = bprev[t];
    __syncthreads();

    int i = blockIdx.x * blockDim.x + t;
    if (i >= NN) return;

    float xin[FIN];
    const float4* ip = (const float4*)(in + (size_t)i * FIN);
#pragma unroll
    for (int c = 0; c < FIN / 4; c++) {
        float4 v = ip[c];
        xin[4 * c + 0] = v.x; xin[4 * c + 1] = v.y;
        xin[4 * c + 2] = v.z; xin[4 * c + 3] = v.w;
    }
#pragma unroll
    for (int k = 0; k < FIN; k++) {
        float v = xin[k];
        if (HASB) v += sb[k];
        if (ACT) v = fmaxf(v, 0.0f);
        xin[k] = v;
    }

    float o[FOUT];
#pragma unroll
    for (int f = 0; f < FOUT; f++) o[f] = 0.0f;
#pragma unroll
    for (int k = 0; k < FIN; k++) {
#pragma unroll
        for (int f = 0; f < FOUT; f++) o[f] = fmaf(xin[k], sW[k * FOUT + f], o[f]);
    }

    float4* xp = (float4*)(g_X + (size_t)i * FOUT);
#pragma unroll
    for (int c = 0; c < FOUT / 4; c++) {
        float4 v;
        v.x = o[4 * c + 0]; v.y = o[4 * c + 1];
        v.z = o[4 * c + 2]; v.w = o[4 * c + 3];
        xp[c] = v;
    }
}

// ---- pull aggregation: agg[i] = X[i]*dis[i]^2 + sum_e X[src_e]*norm_e -------
// thread = (node, 4-feature chunk); chunk is fastest -> gathers of the 4
// threads of one node cover 64 contiguous bytes of the src row.
template <int FOUT, int OUTSEL>
__global__ void gather_kernel() {
    constexpr int C = FOUT / 4;
    int idx = blockIdx.x * blockDim.x + threadIdx.x;
    if (idx >= NN * C) return;
    int i = idx / C;
    int c = idx - i * C;

    int beg = g_rowptr[i];
    int n = g_cnt[i];
    float dv = g_dis[i];
    float d2 = dv * dv;

    const float4* X4 = (const float4*)g_X;
    float4 a = X4[(size_t)i * C + c];
    float4 acc;
    acc.x = a.x * d2; acc.y = a.y * d2; acc.z = a.z * d2; acc.w = a.w * d2;

    const int2* ep = g_epack;
    for (int k = 0; k < n; k++) {
        int2 p = ep[beg + k];
        float nm = __int_as_float(p.y);
        float4 v = X4[(size_t)p.x * C + c];
        acc.x = fmaf(v.x, nm, acc.x);
        acc.y = fmaf(v.y, nm, acc.y);
        acc.z = fmaf(v.z, nm, acc.z);
        acc.w = fmaf(v.w, nm, acc.w);
    }

    float4* agg4 = (float4*)((OUTSEL == 1) ? g_A : g_B);
    agg4[idx] = acc;
}

// ---- epilogue: d_out = sigmoid(g_B + b4) ------------------------------------
__global__ void epilogue_kernel(float4* __restrict__ out, const float* __restrict__ b4) {
    int q = blockIdx.x * blockDim.x + threadIdx.x;   // float4 index
    if (q >= NN * 12 / 4) return;
    const float4* bp = (const float4*)g_B;
    float4 v = bp[q];
    int base = (4 * q) % 12;  // in {0,4,8}
    float4 r;
    r.x = 1.0f / (1.0f + expf(-(v.x + b4[base + 0])));
    r.y = 1.0f / (1.0f + expf(-(v.y + b4[base + 1])));
    r.z = 1.0f / (1.0f + expf(-(v.z + b4[base + 2])));
    r.w = 1.0f / (1.0f + expf(-(v.w + b4[base + 3])));
    out[q] = r;
}

// ---- launch -----------------------------------------------------------------
extern "C" void kernel_launch(void* const* d_in, const int* in_sizes, int n_in,
                              void* d_out, int out_size) {
    const float* x  = (const float*)d_in[0];
    const int*   ei = (const int*)d_in[1];   // int32 edge_index [2, E]
    const float* W1 = (const float*)d_in[2]; const float* b1 = (const float*)d_in[3];
    const float* W2 = (const float*)d_in[4]; const float* b2 = (const float*)d_in[5];
    const float* W3 = (const float*)d_in[6]; const float* b3 = (const float*)d_in[7];
    const float* W4 = (const float*)d_in[8]; const float* b4 = (const float*)d_in[9];
    float* out = (float*)d_out;

    const int BT = 256;
    const int gN = (NN + BT - 1) / BT;
    const int gE = (NE + BT - 1) / BT;
    auto gG = [&](int fout) { return (NN * (fout / 4) + BT - 1) / BT; };

    // degree + normalization + CSR (rebuilt every call: deterministic inputs)
    zero_cnt_kernel<<<gN, BT>>>();
    count_deg_kernel<<<gE, BT>>>(ei);
    dis_kernel<<<gN, BT>>>();
    scan1_kernel<<<NBLK, 1024>>>();
    scan2_kernel<<<1, 1>>>();
    scan3_kernel<<<gN, BT>>>();
    fill_csr_kernel<<<gE, BT>>>(ei);

    // Layer 1: x -> W1 -> X ; gather -> A
    lin_kernel<12, 16, 0, 0, 0><<<gN, BT>>>(x, W1, 0);
    gather_kernel<16, 1><<<gG(16), BT>>>();

    // Layer 2: relu(A + b1) -> W2 -> X ; gather -> B
    lin_kernel<16, 8, 1, 1, 1><<<gN, BT>>>(0, W2, b1);
    gather_kernel<8, 2><<<gG(8), BT>>>();

    // Layer 3: (B + b2) -> W3 -> X ; gather -> A
    lin_kernel<8, 16, 0, 1, 2><<<gN, BT>>>(0, W3, b2);
    gather_kernel<16, 1><<<gG(16), BT>>>();

    // Layer 4: relu(A + b3) -> W4 -> X ; gather -> B
    lin_kernel<16, 12, 1, 1, 1><<<gN, BT>>>(0, W4, b3);
    gather_kernel<12, 2><<<gG(12), BT>>>();

    // out = sigmoid(B + b4)
    epilogue_kernel<<<(NN * 12 / 4 + BT - 1) / BT, BT>>>((float4*)out, b4);
}

// round 8
// speedup vs baseline: 2.7586x; 1.0760x over previous
#include <cuda_runtime.h>
#include <math.h>

#define NN 200000
#define NE 5000000
#define NBLK ((NN + 1023) / 1024)   // scan blocks (196)

// ---- scratch: plain __device__ globals -------------------------------------
__device__ int   g_cnt[NN];      // in-degree (without self-loop)
__device__ int   g_rowptr[NN];   // CSR row start
__device__ int   g_woff[NN];     // fill cursor
__device__ int   g_bsum[NBLK + 8];
__device__ int   g_boff[NBLK + 8];
__device__ float g_dis[NN];
__device__ int2  g_epack[NE];    // {src, norm-bits} bucketed by dst
__device__ float g_A[NN * 16];   // X ping
__device__ float g_B[NN * 16];   // X pong

// ---- degree ----------------------------------------------------------------
__global__ void zero_cnt_kernel() {
    int i = blockIdx.x * blockDim.x + threadIdx.x;
    if (i < NN) g_cnt[i] = 0;
}

__global__ void count_deg_kernel(const int* __restrict__ ei) {
    int e = blockIdx.x * blockDim.x + threadIdx.x;
    if (e < NE) {
        int d = ei[NE + e];
        if ((unsigned)d < NN) atomicAdd(&g_cnt[d], 1);
    }
}

__global__ void dis_kernel() {
    int i = blockIdx.x * blockDim.x + threadIdx.x;
    if (i < NN) g_dis[i] = rsqrtf((float)(g_cnt[i] + 1));  // self-loop included
}

// ---- exclusive prefix sum of g_cnt -> g_rowptr ------------------------------
__global__ void scan1_kernel() {           // 1024 threads/block
    __shared__ int s[1024];
    int gid = blockIdx.x * 1024 + threadIdx.x;
    int v = (gid < NN) ? g_cnt[gid] : 0;
    s[threadIdx.x] = v;
    __syncthreads();
    for (int off = 1; off < 1024; off <<= 1) {
        int t = (threadIdx.x >= off) ? s[threadIdx.x - off] : 0;
        __syncthreads();
        s[threadIdx.x] += t;
        __syncthreads();
    }
    if (gid < NN) g_rowptr[gid] = s[threadIdx.x] - v;  // exclusive within block
    if (threadIdx.x == 1023) g_bsum[blockIdx.x] = s[1023];
}

__global__ void scan2_kernel() {
    int acc = 0;
    for (int b = 0; b < NBLK; b++) { g_boff[b] = acc; acc += g_bsum[b]; }
}

__global__ void scan3_kernel() {
    int gid = blockIdx.x * blockDim.x + threadIdx.x;
    if (gid < NN) {
        int r = g_rowptr[gid] + g_boff[gid >> 10];
        g_rowptr[gid] = r;
        g_woff[gid] = r;
    }
}

// ---- CSR fill: bucket edges by dst, precompute norm -------------------------
__global__ void fill_csr_kernel(const int* __restrict__ ei) {
    int e = blockIdx.x * blockDim.x + threadIdx.x;
    if (e >= NE) return;
    int s = ei[e];
    int d = ei[NE + e];
    if ((unsigned)s >= NN || (unsigned)d >= NN) return;  // trap-proof guard
    float nm = g_dis[s] * g_dis[d];
    int pos = atomicAdd(&g_woff[d], 1);
    g_epack[pos] = make_int2(s, __float_as_int(nm));
}

// ---- layer 1 linear: X1 = x @ W1  (into g_A) --------------------------------
__global__ void lin1_kernel(const float* __restrict__ in, const float* __restrict__ W) {
    constexpr int FIN = 12, FOUT = 16;
    __shared__ float sW[FIN * FOUT];
    int t = threadIdx.x;
    if (t < FIN * FOUT) sW[t] = W[t];
    __syncthreads();

    int i = blockIdx.x * blockDim.x + t;
    if (i >= NN) return;

    float xin[FIN];
    const float4* ip = (const float4*)(in + (size_t)i * FIN);
#pragma unroll
    for (int c = 0; c < FIN / 4; c++) {
        float4 v = ip[c];
        xin[4 * c + 0] = v.x; xin[4 * c + 1] = v.y;
        xin[4 * c + 2] = v.z; xin[4 * c + 3] = v.w;
    }
    float o[FOUT];
#pragma unroll
    for (int f = 0; f < FOUT; f++) o[f] = 0.0f;
#pragma unroll
    for (int k = 0; k < FIN; k++)
#pragma unroll
        for (int f = 0; f < FOUT; f++) o[f] = fmaf(xin[k], sW[k * FOUT + f], o[f]);

    float4* xp = (float4*)(g_A + (size_t)i * FOUT);
#pragma unroll
    for (int c = 0; c < FOUT / 4; c++) {
        float4 v;
        v.x = o[4 * c + 0]; v.y = o[4 * c + 1];
        v.z = o[4 * c + 2]; v.w = o[4 * c + 3];
        xp[c] = v;
    }
}

// ---- unrolled edge aggregation (per 4-feature chunk) ------------------------
template <int C>
__device__ __forceinline__ float4 aggregate_chunk(const float4* __restrict__ X4,
                                                  int i, int c) {
    int beg = g_rowptr[i];
    int n = g_cnt[i];
    float dv = g_dis[i];
    float d2 = dv * dv;
    float4 a = X4[(size_t)i * C + c];
    float4 acc;
    acc.x = a.x * d2; acc.y = a.y * d2; acc.z = a.z * d2; acc.w = a.w * d2;

    const int2* ep = g_epack + beg;
    int k = 0;
    for (; k + 4 <= n; k += 4) {
        int2 p0 = ep[k], p1 = ep[k + 1], p2 = ep[k + 2], p3 = ep[k + 3];
        float4 v0 = X4[(size_t)p0.x * C + c];
        float4 v1 = X4[(size_t)p1.x * C + c];
        float4 v2 = X4[(size_t)p2.x * C + c];
        float4 v3 = X4[(size_t)p3.x * C + c];
        float n0 = __int_as_float(p0.y), n1 = __int_as_float(p1.y);
        float n2 = __int_as_float(p2.y), n3 = __int_as_float(p3.y);
        acc.x = fmaf(v0.x, n0, acc.x); acc.y = fmaf(v0.y, n0, acc.y);
        acc.z = fmaf(v0.z, n0, acc.z); acc.w = fmaf(v0.w, n0, acc.w);
        acc.x = fmaf(v1.x, n1, acc.x); acc.y = fmaf(v1.y, n1, acc.y);
        acc.z = fmaf(v1.z, n1, acc.z); acc.w = fmaf(v1.w, n1, acc.w);
        acc.x = fmaf(v2.x, n2, acc.x); acc.y = fmaf(v2.y, n2, acc.y);
        acc.z = fmaf(v2.z, n2, acc.z); acc.w = fmaf(v2.w, n2, acc.w);
        acc.x = fmaf(v3.x, n3, acc.x); acc.y = fmaf(v3.y, n3, acc.y);
        acc.z = fmaf(v3.z, n3, acc.z); acc.w = fmaf(v3.w, n3, acc.w);
    }
    for (; k < n; k++) {
        int2 p = ep[k];
        float nm = __int_as_float(p.y);
        float4 v = X4[(size_t)p.x * C + c];
        acc.x = fmaf(v.x, nm, acc.x); acc.y = fmaf(v.y, nm, acc.y);
        acc.z = fmaf(v.z, nm, acc.z); acc.w = fmaf(v.w, nm, acc.w);
    }
    return acc;
}

// ---- fused: gather layer L -> +b, act -> @W(L+1) -> X_{L+1} -----------------
// C = FIN/4 chunk-threads per node (C in {2,4}: whole warp groups, shuffles OK)
// INSEL=1: read g_A write g_B ; INSEL=2: read g_B write g_A
template <int FIN, int FOUT, int ACT, int INSEL>
__global__ void fused_kernel(const float* __restrict__ W, const float* __restrict__ bias) {
    constexpr int C = FIN / 4;
    constexpr int FPL = FOUT / C;   // output features per lane
    const float4* X4 = (const float4*)((INSEL == 1) ? g_A : g_B);
    float* Xout = (INSEL == 1) ? g_B : g_A;

    __shared__ float sW[FIN * FOUT];
    __shared__ float sb[16];
    int t = threadIdx.x;
    if (t < FIN * FOUT) sW[t] = W[t];
    if (t < FIN) sb[t] = bias[t];
    __syncthreads();

    int idx = blockIdx.x * blockDim.x + t;
    if (idx >= NN * C) return;    // exits only in whole-warp groups (NN*C % 32 == 0)
    int i = idx / C;
    int c = idx - i * C;

    float4 acc = aggregate_chunk<C>(X4, i, c);

    // assemble full aggregate row via butterfly exchange among the C lanes
    float row[FIN];
    row[4 * c + 0] = acc.x; row[4 * c + 1] = acc.y;
    row[4 * c + 2] = acc.z; row[4 * c + 3] = acc.w;
#pragma unroll
    for (int j = 1; j < C; j++) {
        int cc = c ^ j;
        row[4 * cc + 0] = __shfl_xor_sync(0xffffffffu, acc.x, j);
        row[4 * cc + 1] = __shfl_xor_sync(0xffffffffu, acc.y, j);
        row[4 * cc + 2] = __shfl_xor_sync(0xffffffffu, acc.z, j);
        row[4 * cc + 3] = __shfl_xor_sync(0xffffffffu, acc.w, j);
    }

    // bias + activation, then this lane's FPL output columns
    float h[FIN];
#pragma unroll
    for (int k = 0; k < FIN; k++) {
        float v = row[k] + sb[k];
        h[k] = ACT ? fmaxf(v, 0.0f) : v;
    }
    float o[FPL];
#pragma unroll
    for (int f = 0; f < FPL; f++) o[f] = 0.0f;
#pragma unroll
    for (int k = 0; k < FIN; k++)
#pragma unroll
        for (int f = 0; f < FPL; f++)
            o[f] = fmaf(h[k], sW[k * FOUT + c * FPL + f], o[f]);

    float* op = Xout + (size_t)i * FOUT + c * FPL;
#pragma unroll
    for (int f = 0; f < FPL; f++) op[f] = o[f];
}

// ---- final: gather layer 4 (FIN=12, C=3) -> sigmoid(+b4) -> d_out -----------
__global__ void final_kernel(float4* __restrict__ out, const float* __restrict__ b4) {
    int idx = blockIdx.x * blockDim.x + threadIdx.x;
    if (idx >= NN * 3) return;
    int i = idx / 3;
    int c = idx - i * 3;

    float4 acc = aggregate_chunk<3>((const float4*)g_B, i, c);

    float b0 = b4[4 * c + 0], b1 = b4[4 * c + 1];
    float b2 = b4[4 * c + 2], b3 = b4[4 * c + 3];
    float4 r;
    r.x = 1.0f / (1.0f + expf(-(acc.x + b0)));
    r.y = 1.0f / (1.0f + expf(-(acc.y + b1)));
    r.z = 1.0f / (1.0f + expf(-(acc.z + b2)));
    r.w = 1.0f / (1.0f + expf(-(acc.w + b3)));
    out[idx] = r;
}

// ---- launch -----------------------------------------------------------------
extern "C" void kernel_launch(void* const* d_in, const int* in_sizes, int n_in,
                              void* d_out, int out_size) {
    const float* x  = (const float*)d_in[0];
    const int*   ei = (const int*)d_in[1];   // int32 edge_index [2, E]
    const float* W1 = (const float*)d_in[2]; const float* b1 = (const float*)d_in[3];
    const float* W2 = (const float*)d_in[4]; const float* b2 = (const float*)d_in[5];
    const float* W3 = (const float*)d_in[6]; const float* b3 = (const float*)d_in[7];
    const float* W4 = (const float*)d_in[8]; const float* b4 = (const float*)d_in[9];
    float* out = (float*)d_out;

    const int BT = 256;
    const int gN = (NN + BT - 1) / BT;
    const int gE = (NE + BT - 1) / BT;

    // degree + normalization + CSR (rebuilt every call: deterministic)
    zero_cnt_kernel<<<gN, BT>>>();
    count_deg_kernel<<<gE, BT>>>(ei);
    dis_kernel<<<gN, BT>>>();
    scan1_kernel<<<NBLK, 1024>>>();
    scan2_kernel<<<1, 1>>>();
    scan3_kernel<<<gN, BT>>>();
    fill_csr_kernel<<<gE, BT>>>(ei);

    // L1 linear: X1 = x @ W1 -> g_A
    lin1_kernel<<<gN, BT>>>(x, W1);
    // gather L1 -> relu(+b1) -> @W2 -> X2 (g_B)
    fused_kernel<16, 8, 1, 1><<<(NN * 4 + BT - 1) / BT, BT>>>(W2, b1);
    // gather L2 -> (+b2) -> @W3 -> X3 (g_A)
    fused_kernel<8, 16, 0, 2><<<(NN * 2 + BT - 1) / BT, BT>>>(W3, b2);
    // gather L3 -> relu(+b3) -> @W4 -> X4 (g_B)
    fused_kernel<16, 12, 1, 1><<<(NN * 4 + BT - 1) / BT, BT>>>(W4, b3);
    // gather L4 -> sigmoid(+b4) -> d_out
    final_kernel<<<(NN * 3 + BT - 1) / BT, BT>>>((float4*)out, b4);
}

// round 11
// speedup vs baseline: 3.0626x; 1.1102x over previous
#include <cuda_runtime.h>
#include <math.h>

#define NN 200000
#define NE 5000000
#define NBLK ((NN + 1023) / 1024)   // scan blocks (196)

// ---- scratch ----------------------------------------------------------------
__device__ int    g_cnt[NN];      // in-degree (without self-loop)
__device__ int    g_rowptr[NN];   // CSR row start
__device__ int    g_woff[NN];     // fill cursor
__device__ int    g_bsum[NBLK + 8];
__device__ int    g_boff[NBLK + 8];
__device__ float  g_dis[NN];
__device__ int    g_esrc[NE];     // src ids bucketed by dst (norm factorized out)
__device__ float  g_A[NN * 16];   // Xs ping (dis-prescaled, fp32)
__device__ float  g_B[NN * 16];   // Xs pong

// ---- degree ----------------------------------------------------------------
__global__ void zero_cnt_kernel() {
    int i = blockIdx.x * blockDim.x + threadIdx.x;
    if (i < NN) g_cnt[i] = 0;
}

__global__ void count_deg_kernel(const int* __restrict__ ei) {
    int e = blockIdx.x * blockDim.x + threadIdx.x;
    if (e < NE) {
        int d = ei[NE + e];
        if ((unsigned)d < NN) atomicAdd(&g_cnt[d], 1);
    }
}

__global__ void dis_kernel() {
    int i = blockIdx.x * blockDim.x + threadIdx.x;
    if (i < NN) g_dis[i] = rsqrtf((float)(g_cnt[i] + 1));  // self-loop included
}

// ---- exclusive prefix sum of g_cnt -> g_rowptr ------------------------------
__global__ void scan1_kernel() {
    __shared__ int s[1024];
    int gid = blockIdx.x * 1024 + threadIdx.x;
    int v = (gid < NN) ? g_cnt[gid] : 0;
    s[threadIdx.x] = v;
    __syncthreads();
    for (int off = 1; off < 1024; off <<= 1) {
        int t = (threadIdx.x >= off) ? s[threadIdx.x - off] : 0;
        __syncthreads();
        s[threadIdx.x] += t;
        __syncthreads();
    }
    if (gid < NN) g_rowptr[gid] = s[threadIdx.x] - v;
    if (threadIdx.x == 1023) g_bsum[blockIdx.x] = s[1023];
}

__global__ void scan2_kernel() {
    int acc = 0;
    for (int b = 0; b < NBLK; b++) { g_boff[b] = acc; acc += g_bsum[b]; }
}

__global__ void scan3_kernel() {
    int gid = blockIdx.x * blockDim.x + threadIdx.x;
    if (gid < NN) {
        int r = g_rowptr[gid] + g_boff[gid >> 10];
        g_rowptr[gid] = r;
        g_woff[gid] = r;
    }
}

// ---- CSR fill: bucket src ids by dst ----------------------------------------
__global__ void fill_csr_kernel(const int* __restrict__ ei) {
    int e = blockIdx.x * blockDim.x + threadIdx.x;
    if (e >= NE) return;
    int s = ei[e];
    int d = ei[NE + e];
    if ((unsigned)s >= NN || (unsigned)d >= NN) return;  // trap-proof guard
    int pos = atomicAdd(&g_woff[d], 1);
    g_esrc[pos] = s;
}

// ---- layer 1 linear: Xs1 = dis * (x @ W1) -> g_A ----------------------------
__global__ void lin1_kernel(const float* __restrict__ in, const float* __restrict__ W) {
    constexpr int FIN = 12, FOUT = 16;
    __shared__ float sW[FIN * FOUT];
    int t = threadIdx.x;
    if (t < FIN * FOUT) sW[t] = W[t];
    __syncthreads();

    int i = blockIdx.x * blockDim.x + t;
    if (i >= NN) return;

    float xin[FIN];
    const float4* ip = (const float4*)(in + (size_t)i * FIN);
#pragma unroll
    for (int c = 0; c < FIN / 4; c++) {
        float4 v = ip[c];
        xin[4 * c + 0] = v.x; xin[4 * c + 1] = v.y;
        xin[4 * c + 2] = v.z; xin[4 * c + 3] = v.w;
    }
    float o[FOUT];
#pragma unroll
    for (int f = 0; f < FOUT; f++) o[f] = 0.0f;
#pragma unroll
    for (int k = 0; k < FIN; k++)
#pragma unroll
        for (int f = 0; f < FOUT; f++) o[f] = fmaf(xin[k], sW[k * FOUT + f], o[f]);

    float dv = g_dis[i];
    float4* xp = (float4*)(g_A + (size_t)i * FOUT);
#pragma unroll
    for (int c = 0; c < FOUT / 4; c++) {
        float4 v;
        v.x = o[4 * c + 0] * dv; v.y = o[4 * c + 1] * dv;
        v.z = o[4 * c + 2] * dv; v.w = o[4 * c + 3] * dv;
        xp[c] = v;
    }
}

// ---- edge aggregation of one 4-feature chunk (pure adds, no per-edge mul) ---
template <int C>
__device__ __forceinline__ float4 aggregate_chunk(const float4* __restrict__ Xc,
                                                  int i, int c) {
    int beg = g_rowptr[i];
    int n = g_cnt[i];
    float4 acc = Xc[(size_t)i * C + c];  // self term (dis-prescaled)

    const int* ep = g_esrc + beg;
    int k = 0;
    for (; k + 4 <= n; k += 4) {
        int s0 = ep[k], s1 = ep[k + 1], s2 = ep[k + 2], s3 = ep[k + 3];
        float4 v0 = Xc[(size_t)s0 * C + c];
        float4 v1 = Xc[(size_t)s1 * C + c];
        float4 v2 = Xc[(size_t)s2 * C + c];
        float4 v3 = Xc[(size_t)s3 * C + c];
        acc.x += (v0.x + v1.x) + (v2.x + v3.x);
        acc.y += (v0.y + v1.y) + (v2.y + v3.y);
        acc.z += (v0.z + v1.z) + (v2.z + v3.z);
        acc.w += (v0.w + v1.w) + (v2.w + v3.w);
    }
    for (; k < n; k++) {
        float4 v = Xc[(size_t)ep[k] * C + c];
        acc.x += v.x; acc.y += v.y; acc.z += v.z; acc.w += v.w;
    }
    return acc;
}

// ---- fused: gather L -> *dis, +b, act -> @W -> *dis -> Xs_{L+1} -------------
// C = FIN/4 chunk-threads per node (C in {2,4})
// INSEL=1: read g_A write g_B ; INSEL=2: read g_B write g_A
template <int FIN, int FOUT, int ACT, int INSEL>
__global__ void fused_kernel(const float* __restrict__ W, const float* __restrict__ bias) {
    constexpr int C = FIN / 4;
    constexpr int FPL = FOUT / C;   // output features per lane
    const float4* Xc = (const float4*)((INSEL == 1) ? g_A : g_B);
    float* Xout = (INSEL == 1) ? g_B : g_A;

    __shared__ float sW[FIN * FOUT];
    __shared__ float sb[16];
    int t = threadIdx.x;
    if (t < FIN * FOUT) sW[t] = W[t];
    if (t < FIN) sb[t] = bias[t];
    __syncthreads();

    int idx = blockIdx.x * blockDim.x + t;
    if (idx >= NN * C) return;    // whole-warp exits (NN*C % 32 == 0)
    int i = idx / C;
    int c = idx - i * C;

    float4 acc = aggregate_chunk<C>(Xc, i, c);
    float dv = g_dis[i];

    // assemble full aggregate row via butterfly among the C lanes
    float row[FIN];
    row[4 * c + 0] = acc.x; row[4 * c + 1] = acc.y;
    row[4 * c + 2] = acc.z; row[4 * c + 3] = acc.w;
#pragma unroll
    for (int j = 1; j < C; j++) {
        int cc = c ^ j;
        row[4 * cc + 0] = __shfl_xor_sync(0xffffffffu, acc.x, j);
        row[4 * cc + 1] = __shfl_xor_sync(0xffffffffu, acc.y, j);
        row[4 * cc + 2] = __shfl_xor_sync(0xffffffffu, acc.z, j);
        row[4 * cc + 3] = __shfl_xor_sync(0xffffffffu, acc.w, j);
    }

    // agg = dis * row ; h = act(agg + b) ; o = h @ W[:, lane cols] ; store dis*o
    float h[FIN];
#pragma unroll
    for (int k = 0; k < FIN; k++) {
        float v = fmaf(dv, row[k], sb[k]);
        h[k] = ACT ? fmaxf(v, 0.0f) : v;
    }
    float o[FPL];
#pragma unroll
    for (int f = 0; f < FPL; f++) o[f] = 0.0f;
#pragma unroll
    for (int k = 0; k < FIN; k++)
#pragma unroll
        for (int f = 0; f < FPL; f++)
            o[f] = fmaf(h[k], sW[k * FOUT + c * FPL + f], o[f]);

    float* op = Xout + (size_t)i * FOUT + c * FPL;
#pragma unroll
    for (int f = 0; f < FPL; f++) op[f] = o[f] * dv;
}

// ---- final: gather L4 (FIN=12, C=3) -> sigmoid(dis*row + b4) -> d_out -------
__global__ void final_kernel(float4* __restrict__ out, const float* __restrict__ b4) {
    int idx = blockIdx.x * blockDim.x + threadIdx.x;
    if (idx >= NN * 3) return;
    int i = idx / 3;
    int c = idx - i * 3;

    float4 acc = aggregate_chunk<3>((const float4*)g_B, i, c);
    float dv = g_dis[i];

    float4 r;
    r.x = 1.0f / (1.0f + expf(-fmaf(dv, acc.x, b4[4 * c + 0])));
    r.y = 1.0f / (1.0f + expf(-fmaf(dv, acc.y, b4[4 * c + 1])));
    r.z = 1.0f / (1.0f + expf(-fmaf(dv, acc.z, b4[4 * c + 2])));
    r.w = 1.0f / (1.0f + expf(-fmaf(dv, acc.w, b4[4 * c + 3])));
    out[idx] = r;
}

// ---- launch -----------------------------------------------------------------
extern "C" void kernel_launch(void* const* d_in, const int* in_sizes, int n_in,
                              void* d_out, int out_size) {
    const float* x  = (const float*)d_in[0];
    const int*   ei = (const int*)d_in[1];   // int32 edge_index [2, E]
    const float* W1 = (const float*)d_in[2]; const float* b1 = (const float*)d_in[3];
    const float* W2 = (const float*)d_in[4]; const float* b2 = (const float*)d_in[5];
    const float* W3 = (const float*)d_in[6]; const float* b3 = (const float*)d_in[7];
    const float* W4 = (const float*)d_in[8]; const float* b4 = (const float*)d_in[9];
    float* out = (float*)d_out;

    const int BT = 256;
    const int gN = (NN + BT - 1) / BT;
    const int gE = (NE + BT - 1) / BT;

    zero_cnt_kernel<<<gN, BT>>>();
    count_deg_kernel<<<gE, BT>>>(ei);
    dis_kernel<<<gN, BT>>>();
    scan1_kernel<<<NBLK, 1024>>>();
    scan2_kernel<<<1, 1>>>();
    scan3_kernel<<<gN, BT>>>();
    fill_csr_kernel<<<gE, BT>>>(ei);

    // L1 linear: Xs1 = dis * (x @ W1) -> g_A
    lin1_kernel<<<gN, BT>>>(x, W1);
    // gather L1 -> relu -> @W2 -> Xs2 (g_B)
    fused_kernel<16, 8, 1, 1><<<(NN * 4 + BT - 1) / BT, BT>>>(W2, b1);
    // gather L2 -> @W3 -> Xs3 (g_A)
    fused_kernel<8, 16, 0, 2><<<(NN * 2 + BT - 1) / BT, BT>>>(W3, b2);
    // gather L3 -> relu -> @W4 -> Xs4 (g_B)
    fused_kernel<16, 12, 1, 1><<<(NN * 4 + BT - 1) / BT, BT>>>(W4, b3);
    // gather L4 -> sigmoid -> d_out
    final_kernel<<<(NN * 3 + BT - 1) / BT, BT>>>((float4*)out, b4);
}